// round 11
// baseline (speedup 1.0000x reference)
#include <cuda_runtime.h>
#include <cooperative_groups.h>
#include <cstddef>

namespace cg = cooperative_groups;

#define C_    256
#define HW_   16384
#define B_    32
#define F_    256

#define P_    32
#define RP_   36
#define SPW_  36
#define TPC_  8
#define NB_   64
#define NSLOT_ 3

// Scratch (no allocs allowed)
__device__ float g_part[(size_t)B_ * NB_ * C_];   // 2 MB
__device__ float g_z[B_ * NB_];
__device__ float g_wc[F_ * C_];                   // packed center taps

// ---------------------------------------------------------------------------
__device__ __forceinline__ unsigned smem_u32(const void* p) {
    return (unsigned)__cvta_generic_to_shared(p);
}
__device__ __forceinline__ void cp16(unsigned dst, const float* src) {
    asm volatile("cp.async.cg.shared.global [%0], [%1], 16;" :: "r"(dst), "l"(src));
}
__device__ __forceinline__ void cp_commit() {
    asm volatile("cp.async.commit_group;");
}
__device__ __forceinline__ void cp_wait0() {
    asm volatile("cp.async.wait_group 0;");
}
__device__ __forceinline__ void cp_wait1() {
    asm volatile("cp.async.wait_group 1;");
}

// ---------------------------------------------------------------------------
// Pass 1 (unchanged, at BW ceiling): single HBM pass, 2 CTAs/SM, 3-slot ring,
// depth-2 prefetch, warp-private exp. Also packs out_w center taps for free.
// ---------------------------------------------------------------------------
__global__ __launch_bounds__(256, 2)
void ctx_pass1(const float* __restrict__ x,
               const float* __restrict__ mask_w,
               const float* __restrict__ mask_b,
               const float* __restrict__ out_w) {
    extern __shared__ float sm[];
    __shared__ float spart[8 * SPW_];
    __shared__ __align__(16) float se[8 * SPW_];

    const int b = blockIdx.y, blk = blockIdx.x, t = threadIdx.x;
    const int w = t >> 5, lane = t & 31;
    const int idx = b * NB_ + blk;
    const float* xb = x + (size_t)b * C_ * HW_ + (size_t)blk * (TPC_ * P_);
    const float mb = mask_b[0];

    if (t < 32) {
        int ti = idx * 32 + t;
        int o = ti >> 8, c = ti & 255;
        g_wc[ti] = __ldg(out_w + (size_t)o * (C_ * 25) + (size_t)c * 25 + 12);
    }

    float wv[32];
    {
        float myw = mask_w[w * 32 + lane];
#pragma unroll
        for (int cc = 0; cc < 32; cc++)
            wv[cc] = __shfl_sync(0xffffffffu, myw, cc);
    }

    const unsigned smbase = smem_u32(sm);

    auto load_tile = [&](int tile, int slot) {
        const unsigned dbase = smbase + (unsigned)(slot * C_ * RP_) * 4u;
        const float* src0 = xb + tile * P_;
#pragma unroll
        for (int i = 0; i < 8; i++) {
            int s = i * 256 + t;
            int c = s >> 3, q = s & 7;
            cp16(dbase + (unsigned)(c * RP_ + q * 4) * 4u,
                 src0 + (size_t)c * HW_ + q * 4);
        }
    };

    load_tile(0, 0); cp_commit();
    load_tile(1, 1); cp_commit();

    float acc = 0.f;
    float zw  = 0.f;

    int slot = 0;
#pragma unroll 1
    for (int tile = 0; tile < TPC_; tile++) {
        if (tile < TPC_ - 1) cp_wait1();
        else                 cp_wait0();
        __syncthreads();

        if (tile + 2 < TPC_) {
            int ns = slot + 2; if (ns >= NSLOT_) ns -= NSLOT_;
            load_tile(tile + 2, ns);
            cp_commit();
        }

        const float* buf = sm + slot * C_ * RP_;

        float lacc = 0.f;
#pragma unroll
        for (int cc = 0; cc < 32; cc++)
            lacc += buf[(w * 32 + cc) * RP_ + lane] * wv[cc];
        spart[w * SPW_ + lane] = lacc;
        __syncthreads();

        {
            float lg = mb;
#pragma unroll
            for (int g2 = 0; g2 < 8; g2++) lg += spart[g2 * SPW_ + lane];
            float e = __expf(lg);
            se[w * SPW_ + lane] = e;
            if (w == 0) {
                float z = e;
#pragma unroll
                for (int o = 16; o; o >>= 1)
                    z += __shfl_xor_sync(0xffffffffu, z, o);
                zw += z;
            }
            __syncwarp();
        }

        const float4* rowv = reinterpret_cast<const float4*>(buf + t * RP_);
        const float4* sev  = reinterpret_cast<const float4*>(se + w * SPW_);
        float a0 = 0.f, a1 = 0.f;
#pragma unroll
        for (int pp = 0; pp < 8; pp++) {
            float4 xv = rowv[pp], ev = sev[pp];
            a0 += xv.x * ev.x + xv.y * ev.y;
            a1 += xv.z * ev.z + xv.w * ev.w;
        }
        acc += a0 + a1;

        slot++; if (slot >= NSLOT_) slot = 0;
    }

    g_part[(size_t)idx * C_ + t] = acc;
    if (t == 0) g_z[idx] = zw;
}

// ---------------------------------------------------------------------------
// Tail: ONE kernel, grid(4, B), cluster(4,1,1). CTA rc of batch b's cluster:
//   combine ctx (redundant) -> 64 rows cm1 -> DSMEM broadcast -> cluster.sync
//   -> LN (redundant) + ReLU -> 64 rows cm2 -> sigmoid -> broadcast -> sync
//   -> gate 64 features (att + packed center taps).
// ---------------------------------------------------------------------------
__global__ __launch_bounds__(256) __cluster_dims__(4, 1, 1)
void tail_kernel(const float* __restrict__ cm1_w, const float* __restrict__ cm1_b,
                 const float* __restrict__ ln_g,  const float* __restrict__ ln_b,
                 const float* __restrict__ cm2_w, const float* __restrict__ cm2_b,
                 const float* __restrict__ out_b, const float* __restrict__ att_w,
                 const float* __restrict__ att_b, float* __restrict__ out) {
    cg::cluster_group cluster = cg::this_cluster();

    __shared__ float sctx[C_];    // full context vector (local copy)
    __shared__ float sh1[C_];     // full h1 (assembled via DSMEM)
    __shared__ float six[C_];     // full input_x (assembled via DSMEM)
    __shared__ float sred[20];

    const int b = blockIdx.y, rc = blockIdx.x, t = threadIdx.x;
    const int w = t >> 5, lane = t & 31;

    // 1/Z
    if (t < 32) {
        float zz = g_z[b * NB_ + t] + g_z[b * NB_ + 32 + t];
#pragma unroll
        for (int o = 16; o; o >>= 1) zz += __shfl_xor_sync(0xffffffffu, zz, o);
        if (t == 0) sred[0] = 1.f / zz;
    }

    // combine partial contexts (thread t = channel t, coalesced over k)
    float acc = 0.f;
    const float* gp = g_part + (size_t)b * NB_ * C_ + t;
#pragma unroll 8
    for (int k = 0; k < NB_; k++) acc += gp[(size_t)k * C_];
    __syncthreads();
    sctx[t] = acc * sred[0];
    __syncthreads();

    // 64 rows of cm1 -> broadcast into every cluster CTA's sh1
#pragma unroll
    for (int i = 0; i < 4; i++) {
        int o0 = rc * 64 + w * 8 + 2 * i, o1 = o0 + 1;
        const float* r0 = cm1_w + (size_t)o0 * C_;
        const float* r1 = cm1_w + (size_t)o1 * C_;
        float p0 = 0.f, p1 = 0.f;
#pragma unroll
        for (int j = 0; j < 8; j++) {
            float v = sctx[j * 32 + lane];
            p0 += r0[j * 32 + lane] * v;
            p1 += r1[j * 32 + lane] * v;
        }
#pragma unroll
        for (int o = 16; o; o >>= 1) {
            p0 += __shfl_xor_sync(0xffffffffu, p0, o);
            p1 += __shfl_xor_sync(0xffffffffu, p1, o);
        }
        if (lane == 0) {
            float v0 = p0 + cm1_b[o0], v1 = p1 + cm1_b[o1];
#pragma unroll
            for (int r = 0; r < 4; r++) {
                float* dst = cluster.map_shared_rank(sh1, r);
                dst[o0] = v0; dst[o1] = v1;
            }
        }
    }
    cluster.sync();

    // LayerNorm (redundant per CTA) + ReLU, in place on sh1
    float h = sh1[t];
    {
        float sum = h, sq = h * h;
#pragma unroll
        for (int o = 16; o; o >>= 1) {
            sum += __shfl_xor_sync(0xffffffffu, sum, o);
            sq  += __shfl_xor_sync(0xffffffffu, sq,  o);
        }
        if (lane == 0) { sred[2 + w] = sum; sred[10 + w] = sq; }
        __syncthreads();
        if (t == 0) {
            float a = 0.f, bb = 0.f;
#pragma unroll
            for (int i = 0; i < 8; i++) { a += sred[2 + i]; bb += sred[10 + i]; }
            sred[0] = a; sred[1] = bb;
        }
        __syncthreads();
        const float mu  = sred[0] * (1.f / C_);
        const float var = sred[1] * (1.f / C_) - mu * mu;
        h = (h - mu) * rsqrtf(var + 1e-5f) * ln_g[t] + ln_b[t];
        h = fmaxf(h, 0.f);
    }
    sh1[t] = h;
    __syncthreads();

    // 64 rows of cm2 -> sigmoid -> broadcast into every CTA's six
#pragma unroll
    for (int i = 0; i < 4; i++) {
        int o0 = rc * 64 + w * 8 + 2 * i, o1 = o0 + 1;
        const float* r0 = cm2_w + (size_t)o0 * C_;
        const float* r1 = cm2_w + (size_t)o1 * C_;
        float p0 = 0.f, p1 = 0.f;
#pragma unroll
        for (int j = 0; j < 8; j++) {
            float v = sh1[j * 32 + lane];
            p0 += r0[j * 32 + lane] * v;
            p1 += r1[j * 32 + lane] * v;
        }
#pragma unroll
        for (int o = 16; o; o >>= 1) {
            p0 += __shfl_xor_sync(0xffffffffu, p0, o);
            p1 += __shfl_xor_sync(0xffffffffu, p1, o);
        }
        if (lane == 0) {
            float v0 = 1.f / (1.f + __expf(-(p0 + cm2_b[o0])));
            float v1 = 1.f / (1.f + __expf(-(p1 + cm2_b[o1])));
#pragma unroll
            for (int r = 0; r < 4; r++) {
                float* dst = cluster.map_shared_rank(six, r);
                dst[o0] = v0; dst[o1] = v1;
            }
        }
    }
    cluster.sync();

    // gate: this CTA's 64 features (att linear + packed center-tap conv)
#pragma unroll
    for (int i = 0; i < 4; i++) {
        int o0 = rc * 64 + w * 8 + 2 * i, o1 = o0 + 1;
        const float* ra0 = att_w + (size_t)o0 * C_;
        const float* ra1 = att_w + (size_t)o1 * C_;
        const float* rc0 = g_wc  + (size_t)o0 * C_;
        const float* rc1 = g_wc  + (size_t)o1 * C_;
        float pa0 = 0.f, pa1 = 0.f, pc0 = 0.f, pc1 = 0.f;
#pragma unroll
        for (int j = 0; j < 8; j++) {
            int c = j * 32 + lane;
            float v = six[c];
            pa0 += ra0[c] * v;
            pa1 += ra1[c] * v;
            pc0 += rc0[c] * v;
            pc1 += rc1[c] * v;
        }
#pragma unroll
        for (int o = 16; o; o >>= 1) {
            pa0 += __shfl_xor_sync(0xffffffffu, pa0, o);
            pa1 += __shfl_xor_sync(0xffffffffu, pa1, o);
            pc0 += __shfl_xor_sync(0xffffffffu, pc0, o);
            pc1 += __shfl_xor_sync(0xffffffffu, pc1, o);
        }
        if (lane == 0) {
            float a0 = 1.f / (1.f + __expf(-(pa0 + att_b[o0])));
            float a1 = 1.f / (1.f + __expf(-(pa1 + att_b[o1])));
            out[b * F_ + o0] = a0 * (pc0 + out_b[o0]);
            out[b * F_ + o1] = a1 * (pc1 + out_b[o1]);
        }
    }
}

extern "C" void kernel_launch(void* const* d_in, const int* in_sizes, int n_in,
                              void* d_out, int out_size) {
    const float* x      = (const float*)d_in[0];
    const float* mask_w = (const float*)d_in[1];
    const float* mask_b = (const float*)d_in[2];
    const float* cm1_w  = (const float*)d_in[3];
    const float* cm1_b  = (const float*)d_in[4];
    const float* ln_g   = (const float*)d_in[5];
    const float* ln_b   = (const float*)d_in[6];
    const float* cm2_w  = (const float*)d_in[7];
    const float* cm2_b  = (const float*)d_in[8];
    const float* out_w  = (const float*)d_in[9];
    const float* out_b  = (const float*)d_in[10];
    const float* att_w  = (const float*)d_in[11];
    const float* att_b  = (const float*)d_in[12];
    float* out = (float*)d_out;

    const int smem1 = NSLOT_ * C_ * RP_ * (int)sizeof(float);  // 110592 B
    cudaFuncSetAttribute(ctx_pass1, cudaFuncAttributeMaxDynamicSharedMemorySize, smem1);

    ctx_pass1<<<dim3(NB_, B_), 256, smem1>>>(x, mask_w, mask_b, out_w);
    tail_kernel<<<dim3(4, B_), 256>>>(cm1_w, cm1_b, ln_g, ln_b, cm2_w, cm2_b,
                                      out_b, att_w, att_b, out);
}